// round 1
// baseline (speedup 1.0000x reference)
#include <cuda_runtime.h>
#include <math.h>

#define B_  32
#define S_  512
#define I_  256
#define H_  1024
#define O_  256
#define L_  3
#define G3H (3*H_)
#define NCTA_REC 128

// ---------------- device scratch (allocation-free) ----------------
__device__ float g_xT[(size_t)S_*B_*I_];        // 16 MB  transposed x -> [s*B+b][i]
__device__ float g_xp[(size_t)S_*B_*G3H];       // 201 MB input projections [s*B+b][3H]
__device__ float g_hs[(size_t)S_*B_*H_];        // 64 MB  layer output sequence [s*B+b][h]
__device__ float g_h [B_*H_];                   // current hidden
__device__ float g_z [B_*H_];                   // z gate
__device__ float g_rh[B_*H_];                   // r*h
__device__ unsigned int g_barcount;
__device__ unsigned int g_bargen;

// ---------------- grid-wide barrier (all CTAs co-resident) ----------------
__device__ __forceinline__ void grid_barrier()
{
    __syncthreads();
    if (threadIdx.x == 0) {
        unsigned int gen = *(volatile unsigned int*)&g_bargen;
        __threadfence();
        if (atomicAdd(&g_barcount, 1u) == gridDim.x - 1u) {
            g_barcount = 0u;
            __threadfence();
            atomicAdd(&g_bargen, 1u);
        } else {
            while (*(volatile unsigned int*)&g_bargen == gen) { __nanosleep(64); }
        }
        __threadfence();
    }
    __syncthreads();
}

// ---------------- transpose x[b][s][i] -> xT[(s*B+b)][i] ----------------
__global__ void transpose_kernel(const float4* __restrict__ x, float4* __restrict__ xT)
{
    int idx = blockIdx.x * blockDim.x + threadIdx.x;   // over S*B*I/4 = 1,048,576
    int i4 = idx & 63;          // I/4 = 64
    int m  = idx >> 6;          // m = s*B + b
    int b  = m & 31;
    int s  = m >> 5;
    xT[idx] = x[(size_t)(b * S_ + s) * 64 + i4];
}

// ---------------- SGEMM: C[m][n] = sum_k A[m][k]*W[n][k] + bias[n] ----------------
// mode 0: C[m*N + n]   (xproj into g_xp)
// mode 1: m=(s*B+b) -> C[(b*S+s)*O + n]  (final output head)
__global__ void __launch_bounds__(256) gemm_kernel(
    const float* __restrict__ A, const float* __restrict__ W,
    const float* __restrict__ bias, float* __restrict__ C,
    int K, int N, int mode)
{
    __shared__ float As[8][128];
    __shared__ float Bs[8][128];

    const int tid  = threadIdx.x;
    const int bx   = blockIdx.x;   // N tile
    const int by   = blockIdx.y;   // M tile
    const int lrow = tid >> 1;
    const int lc4  = (tid & 1) << 2;

    const float* Arow = A + (size_t)(by * 128 + lrow) * K + lc4;
    const float* Wrow = W + (size_t)(bx * 128 + lrow) * K + lc4;

    const int tx = tid & 15;
    const int ty = tid >> 4;

    float acc[8][8];
#pragma unroll
    for (int i = 0; i < 8; i++)
#pragma unroll
        for (int j = 0; j < 8; j++) acc[i][j] = 0.f;

    for (int kt = 0; kt < K; kt += 8) {
        float4 av = *(const float4*)(Arow + kt);
        float4 wv = *(const float4*)(Wrow + kt);
        __syncthreads();
        As[lc4 + 0][lrow] = av.x; As[lc4 + 1][lrow] = av.y;
        As[lc4 + 2][lrow] = av.z; As[lc4 + 3][lrow] = av.w;
        Bs[lc4 + 0][lrow] = wv.x; Bs[lc4 + 1][lrow] = wv.y;
        Bs[lc4 + 2][lrow] = wv.z; Bs[lc4 + 3][lrow] = wv.w;
        __syncthreads();
#pragma unroll
        for (int k = 0; k < 8; k++) {
            float a[8], b[8];
#pragma unroll
            for (int i = 0; i < 8; i++) a[i] = As[k][ty * 8 + i];
#pragma unroll
            for (int j = 0; j < 8; j++) b[j] = Bs[k][tx * 8 + j];
#pragma unroll
            for (int i = 0; i < 8; i++)
#pragma unroll
                for (int j = 0; j < 8; j++) acc[i][j] += a[i] * b[j];
        }
    }

    const int mbase = by * 128 + ty * 8;
    const int nbase = bx * 128 + tx * 8;
    float bb[8];
#pragma unroll
    for (int j = 0; j < 8; j++) bb[j] = bias[nbase + j];

#pragma unroll
    for (int i = 0; i < 8; i++) {
        int m = mbase + i;
#pragma unroll
        for (int j = 0; j < 8; j++) {
            float v = acc[i][j] + bb[j];
            if (mode == 0) {
                C[(size_t)m * N + (nbase + j)] = v;
            } else {
                int b = m & 31, s = m >> 5;
                C[(size_t)((b << 9) + s) * O_ + (nbase + j)] = v;
            }
        }
    }
}

// ---------------- persistent GRU recurrence (one layer) ----------------
// grid = 128 CTAs (1/SM, co-resident), 256 threads, 128 KB dynamic smem.
__global__ void __launch_bounds__(256, 1) gru_rec_kernel(
    const float* __restrict__ Wh,      // [3H][H]
    const float* __restrict__ xp,      // [S*B][3H] (bias folded in)
    float*       __restrict__ hs,      // [S*B][H]
    const float* __restrict__ h0,      // [B][L][H]
    int layer,
    float*       __restrict__ hlast)   // d_out + B*S*O : [B][L][H]
{
    extern __shared__ float sh[];      // 32*1024 floats = 128 KB
    const int tid  = threadIdx.x;
    const int cta  = blockIdx.x;
    const int w    = tid >> 5;
    const int lane = tid & 31;
    const int kq   = lane & 7;         // k-group within warp
    // b handled by this lane's writeback = lane (bq*8 + kq)
    const int b    = lane;

    // init hidden state from h0
    {
        int i = cta * 256 + tid;       // exactly B*H = 32768 threads
        int bb = i >> 10, jj = i & 1023;
        g_h[i] = h0[(bb * L_ + layer) * H_ + jj];
    }
    grid_barrier();

    const float4* sh4 = (const float4*)sh;
    float4*       sh4w = (float4*)sh;

    for (int s = 0; s < S_; s++) {
        // ---- stage h into smem (L2-coherent loads) ----
        {
            const float4* gh4 = (const float4*)g_h;
            for (int i = tid; i < 8192; i += 256) sh4w[i] = __ldcg(gh4 + i);
        }
        __syncthreads();

        // ---- phase A: z and r gates (2048 cols / 128 CTAs = 16; 2 per warp) ----
        {
            const int j0 = cta * 16 + w * 2;
            const int j1 = j0 + 1;
            const float4* W0 = (const float4*)(Wh + (size_t)j0 * H_);
            const float4* W1 = (const float4*)(Wh + (size_t)j1 * H_);
            const int bq = lane >> 3;

            float acc0[8], acc1[8];
#pragma unroll
            for (int bi = 0; bi < 8; bi++) { acc0[bi] = 0.f; acc1[bi] = 0.f; }

#pragma unroll 4
            for (int i = 0; i < 32; i++) {
                int k4 = (i << 3) + kq;            // k-interleave: conflict-free LDS
                float4 w0v = W0[k4];
                float4 w1v = W1[k4];
#pragma unroll
                for (int bi = 0; bi < 8; bi++) {
                    float4 hv = sh4[(((bq << 3) + bi) << 8) + k4];
                    acc0[bi] += hv.x * w0v.x + hv.y * w0v.y + hv.z * w0v.z + hv.w * w0v.w;
                    acc1[bi] += hv.x * w1v.x + hv.y * w1v.y + hv.z * w1v.z + hv.w * w1v.w;
                }
            }
            // reduce across the 8 k-groups (lane bits 0..2)
#pragma unroll
            for (int off = 1; off < 8; off <<= 1) {
#pragma unroll
                for (int bi = 0; bi < 8; bi++) {
                    acc0[bi] += __shfl_xor_sync(0xffffffffu, acc0[bi], off);
                    acc1[bi] += __shfl_xor_sync(0xffffffffu, acc1[bi], off);
                }
            }
            float v0 = 0.f, v1 = 0.f;
#pragma unroll
            for (int bi = 0; bi < 8; bi++) if (kq == bi) { v0 = acc0[bi]; v1 = acc1[bi]; }

            const size_t xpb = (size_t)(s * B_ + b) * G3H;
#pragma unroll
            for (int c = 0; c < 2; c++) {
                int   j = c ? j1 : j0;
                float v = c ? v1 : v0;
                float pre = xp[xpb + j] + v;
                float sg  = 1.f / (1.f + expf(-pre));
                if (j < H_) {
                    g_z[b * H_ + j] = sg;
                } else {
                    int jr = j - H_;
                    g_rh[b * H_ + jr] = sg * sh[b * H_ + jr];
                }
            }
        }
        grid_barrier();

        // ---- stage r*h into smem ----
        {
            const float4* gr4 = (const float4*)g_rh;
            for (int i = tid; i < 8192; i += 256) sh4w[i] = __ldcg(gr4 + i);
        }
        __syncthreads();

        // ---- phase B: g gate + h update (1024 cols / 128 CTAs = 8; 2 per warp, warps 0-3) ----
        if (w < 4) {
            const int j0 = cta * 8 + w * 2;
            const int j1 = j0 + 1;
            const float4* W0 = (const float4*)(Wh + (size_t)(2 * H_ + j0) * H_);
            const float4* W1 = (const float4*)(Wh + (size_t)(2 * H_ + j1) * H_);
            const int bq = lane >> 3;

            float acc0[8], acc1[8];
#pragma unroll
            for (int bi = 0; bi < 8; bi++) { acc0[bi] = 0.f; acc1[bi] = 0.f; }

#pragma unroll 4
            for (int i = 0; i < 32; i++) {
                int k4 = (i << 3) + kq;
                float4 w0v = W0[k4];
                float4 w1v = W1[k4];
#pragma unroll
                for (int bi = 0; bi < 8; bi++) {
                    float4 hv = sh4[(((bq << 3) + bi) << 8) + k4];
                    acc0[bi] += hv.x * w0v.x + hv.y * w0v.y + hv.z * w0v.z + hv.w * w0v.w;
                    acc1[bi] += hv.x * w1v.x + hv.y * w1v.y + hv.z * w1v.z + hv.w * w1v.w;
                }
            }
#pragma unroll
            for (int off = 1; off < 8; off <<= 1) {
#pragma unroll
                for (int bi = 0; bi < 8; bi++) {
                    acc0[bi] += __shfl_xor_sync(0xffffffffu, acc0[bi], off);
                    acc1[bi] += __shfl_xor_sync(0xffffffffu, acc1[bi], off);
                }
            }
            float v0 = 0.f, v1 = 0.f;
#pragma unroll
            for (int bi = 0; bi < 8; bi++) if (kq == bi) { v0 = acc0[bi]; v1 = acc1[bi]; }

            const size_t xpb = (size_t)(s * B_ + b) * G3H + 2 * H_;
#pragma unroll
            for (int c = 0; c < 2; c++) {
                int   j = c ? j1 : j0;
                float v = c ? v1 : v0;
                float g  = tanhf(xp[xpb + j] + v);
                float z  = __ldcg(&g_z[b * H_ + j]);
                float ho = __ldcg(&g_h[b * H_ + j]);
                float hn = z * ho + (1.f - z) * g;
                g_h[b * H_ + j] = hn;
                hs[(size_t)(s * B_ + b) * H_ + j] = hn;
                if (s == S_ - 1) hlast[(b * L_ + layer) * H_ + j] = hn;
            }
        }
        grid_barrier();
    }
}

// ---------------- host launch ----------------
extern "C" void kernel_launch(void* const* d_in, const int* in_sizes, int n_in,
                              void* d_out, int out_size)
{
    const float* x    = (const float*)d_in[0];
    const float* h0   = (const float*)d_in[1];
    const float* Wx0  = (const float*)d_in[2];
    const float* Wh0  = (const float*)d_in[3];
    const float* bh0  = (const float*)d_in[4];
    const float* Wx   = (const float*)d_in[5];
    const float* Wh   = (const float*)d_in[6];
    const float* bh   = (const float*)d_in[7];
    const float* Wout = (const float*)d_in[8];
    const float* bout = (const float*)d_in[9];

    float* out = (float*)d_out;
    float* hid = out + (size_t)B_ * S_ * O_;

    float *p_xT, *p_xp, *p_hs;
    cudaGetSymbolAddress((void**)&p_xT, g_xT);
    cudaGetSymbolAddress((void**)&p_xp, g_xp);
    cudaGetSymbolAddress((void**)&p_hs, g_hs);

    cudaFuncSetAttribute(gru_rec_kernel,
                         cudaFuncAttributeMaxDynamicSharedMemorySize, 131072);

    // 1) transpose x -> [s*B+b][i]
    transpose_kernel<<<4096, 256>>>((const float4*)x, (float4*)p_xT);

    // 2) layer 0
    gemm_kernel<<<dim3(G3H / 128, (S_ * B_) / 128), 256>>>(p_xT, Wx0, bh0, p_xp, I_, G3H, 0);
    gru_rec_kernel<<<NCTA_REC, 256, 131072>>>(Wh0, p_xp, p_hs, h0, 0, hid);

    // 3) layer 1
    gemm_kernel<<<dim3(G3H / 128, (S_ * B_) / 128), 256>>>(p_hs, Wx, bh, p_xp, H_, G3H, 0);
    gru_rec_kernel<<<NCTA_REC, 256, 131072>>>(Wh, p_xp, p_hs, h0, 1, hid);

    // 4) layer 2
    gemm_kernel<<<dim3(G3H / 128, (S_ * B_) / 128), 256>>>(
        p_hs, Wx + (size_t)3 * H_ * H_, bh + 3 * H_, p_xp, H_, G3H, 0);
    gru_rec_kernel<<<NCTA_REC, 256, 131072>>>(
        Wh + (size_t)3 * H_ * H_, p_xp, p_hs, h0, 2, hid);

    // 5) output head -> d_out [B,S,O]
    gemm_kernel<<<dim3(O_ / 128, (S_ * B_) / 128), 256>>>(p_hs, Wout, bout, out, H_, O_, 1);
}

// round 2
// speedup vs baseline: 1.8420x; 1.8420x over previous
#include <cuda_runtime.h>
#include <math.h>

#define B_  32
#define S_  512
#define I_  256
#define H_  1024
#define O_  256
#define L_  3
#define G3H (3*H_)
#define NCTA_REC 128

typedef unsigned long long ull;

// ---------------- f32x2 packed math (sm_103a FFMA2 path) ----------------
__device__ __forceinline__ ull pk2(float x, float y) {
    ull r;
    asm("mov.b64 %0, {%1, %2};" : "=l"(r)
        : "r"(__float_as_uint(x)), "r"(__float_as_uint(y)));
    return r;
}
__device__ __forceinline__ void upk2(ull p, float& x, float& y) {
    unsigned int a, b;
    asm("mov.b64 {%0, %1}, %2;" : "=r"(a), "=r"(b) : "l"(p));
    x = __uint_as_float(a); y = __uint_as_float(b);
}
__device__ __forceinline__ ull ffma2(ull a, ull b, ull c) {
    ull d;
    asm("fma.rn.f32x2 %0, %1, %2, %3;" : "=l"(d) : "l"(a), "l"(b), "l"(c));
    return d;
}
__device__ __forceinline__ ull fadd2(ull a, ull b) {
    ull d;
    asm("add.rn.f32x2 %0, %1, %2;" : "=l"(d) : "l"(a), "l"(b));
    return d;
}

// ---------------- device scratch (allocation-free) ----------------
__device__ float g_xT[(size_t)S_*B_*I_];        // 16 MB  transposed x -> [s*B+b][i]
__device__ float g_xp[(size_t)S_*B_*G3H];       // 201 MB input projections [s*B+b][3H]
__device__ float g_hs[(size_t)S_*B_*H_];        // 64 MB  layer output sequence [s*B+b][h]
__device__ float g_hT [H_*B_];                  // hidden,  [j][b] layout
__device__ float g_rhT[H_*B_];                  // r*h,     [j][b] layout
__device__ unsigned int g_barcount;
__device__ unsigned int g_bargen;

// ---------------- grid-wide barrier (all CTAs co-resident) ----------------
__device__ __forceinline__ void grid_barrier()
{
    __syncthreads();
    if (threadIdx.x == 0) {
        unsigned int gen = *(volatile unsigned int*)&g_bargen;
        __threadfence();
        if (atomicAdd(&g_barcount, 1u) == gridDim.x - 1u) {
            g_barcount = 0u;
            __threadfence();
            atomicAdd(&g_bargen, 1u);
        } else {
            while (*(volatile unsigned int*)&g_bargen == gen) { __nanosleep(32); }
        }
        __threadfence();
    }
    __syncthreads();
}

// ---------------- transpose x[b][s][i] -> xT[(s*B+b)][i] ----------------
__global__ void transpose_kernel(const float4* __restrict__ x, float4* __restrict__ xT)
{
    int idx = blockIdx.x * blockDim.x + threadIdx.x;   // over S*B*I/4
    int i4 = idx & 63;          // I/4 = 64
    int m  = idx >> 6;          // m = s*B + b
    int b  = m & 31;
    int s  = m >> 5;
    xT[idx] = x[(size_t)(b * S_ + s) * 64 + i4];
}

// ---------------- SGEMM: C[m][n] = sum_k A[m][k]*W[n][k] + bias[n] ----------------
// mode 0: C[m*N + n]   (xproj into g_xp)
// mode 1: m=(s*B+b) -> C[(b*S+s)*O + n]  (final output head)
__global__ void __launch_bounds__(256) gemm_kernel(
    const float* __restrict__ A, const float* __restrict__ W,
    const float* __restrict__ bias, float* __restrict__ C,
    int K, int N, int mode)
{
    __shared__ float As[16][128];
    __shared__ float Bs[16][128];

    const int tid  = threadIdx.x;
    const int bx   = blockIdx.x;   // N tile
    const int by   = blockIdx.y;   // M tile
    const int lrow = tid >> 1;
    const int lc4  = (tid & 1) << 2;

    const float* Arow = A + (size_t)(by * 128 + lrow) * K + lc4;
    const float* Wrow = W + (size_t)(bx * 128 + lrow) * K + lc4;

    const int tx = tid & 15;
    const int ty = tid >> 4;

    ull acc2[8][4];
#pragma unroll
    for (int i = 0; i < 8; i++)
#pragma unroll
        for (int j = 0; j < 4; j++) acc2[i][j] = 0ull;

    for (int kt = 0; kt < K; kt += 16) {
        float4 a0 = *(const float4*)(Arow + kt);
        float4 a1 = *(const float4*)(Arow + kt + 8);
        float4 w0 = *(const float4*)(Wrow + kt);
        float4 w1 = *(const float4*)(Wrow + kt + 8);
        __syncthreads();
        As[lc4 + 0][lrow] = a0.x; As[lc4 + 1][lrow] = a0.y;
        As[lc4 + 2][lrow] = a0.z; As[lc4 + 3][lrow] = a0.w;
        As[lc4 + 8][lrow] = a1.x; As[lc4 + 9][lrow] = a1.y;
        As[lc4 +10][lrow] = a1.z; As[lc4 +11][lrow] = a1.w;
        Bs[lc4 + 0][lrow] = w0.x; Bs[lc4 + 1][lrow] = w0.y;
        Bs[lc4 + 2][lrow] = w0.z; Bs[lc4 + 3][lrow] = w0.w;
        Bs[lc4 + 8][lrow] = w1.x; Bs[lc4 + 9][lrow] = w1.y;
        Bs[lc4 +10][lrow] = w1.z; Bs[lc4 +11][lrow] = w1.w;
        __syncthreads();
#pragma unroll
        for (int k = 0; k < 16; k++) {
            float4 av0 = *(const float4*)&As[k][ty * 8];
            float4 av1 = *(const float4*)&As[k][ty * 8 + 4];
            float4 bv0 = *(const float4*)&Bs[k][tx * 8];
            float4 bv1 = *(const float4*)&Bs[k][tx * 8 + 4];
            ull pb0 = pk2(bv0.x, bv0.y);
            ull pb1 = pk2(bv0.z, bv0.w);
            ull pb2 = pk2(bv1.x, bv1.y);
            ull pb3 = pk2(bv1.z, bv1.w);
            float a_[8] = {av0.x, av0.y, av0.z, av0.w, av1.x, av1.y, av1.z, av1.w};
#pragma unroll
            for (int i = 0; i < 8; i++) {
                ull pa = pk2(a_[i], a_[i]);
                acc2[i][0] = ffma2(pa, pb0, acc2[i][0]);
                acc2[i][1] = ffma2(pa, pb1, acc2[i][1]);
                acc2[i][2] = ffma2(pa, pb2, acc2[i][2]);
                acc2[i][3] = ffma2(pa, pb3, acc2[i][3]);
            }
        }
    }

    const int mbase = by * 128 + ty * 8;
    const int nbase = bx * 128 + tx * 8;
    float bb[8];
#pragma unroll
    for (int j = 0; j < 8; j++) bb[j] = bias[nbase + j];

#pragma unroll
    for (int i = 0; i < 8; i++) {
        int m = mbase + i;
        float cv[8];
#pragma unroll
        for (int j = 0; j < 4; j++) upk2(acc2[i][j], cv[2*j], cv[2*j+1]);
#pragma unroll
        for (int j = 0; j < 8; j++) {
            float v = cv[j] + bb[j];
            if (mode == 0) {
                C[(size_t)m * N + (nbase + j)] = v;
            } else {
                int b = m & 31, s = m >> 5;
                C[(size_t)((b << 9) + s) * O_ + (nbase + j)] = v;
            }
        }
    }
}

// ---------------- persistent GRU recurrence (one layer) ----------------
// grid = 128 CTAs (1/SM, co-resident), 256 threads = 8 warps, 224 KB dynamic smem.
// CTA owns columns [cta*8, cta*8+8) of each gate.
// warp = g*4 + r : g = column-half (phase A: 8 cols each / phase B: 4 cols each),
//                  r = k-quarter (256 k each). lane = batch b.
__global__ void __launch_bounds__(256, 1) gru_rec_kernel(
    const float* __restrict__ Wh,      // [3H][H]
    const float* __restrict__ xp,      // [S*B][3H] (bias folded in)
    float*       __restrict__ hs,      // [S*B][H]
    const float* __restrict__ h0,      // [B][L][H]
    int layer,
    float*       __restrict__ hlast)   // d_out + B*S*O : [B][L][H]
{
    extern __shared__ float sh[];
    float* w_sA = sh;                  // [1024][16] z cols 0..7, r cols 8..15  (64 KB)
    float* w_g  = sh + 16384;          // [1024][8]                              (32 KB)
    float* hbuf = sh + 24576;          // [1024][32]                             (128 KB)
    __shared__ float s_z[B_ * 8];      // z values [b][c]

    const int tid  = threadIdx.x;
    const int cta  = blockIdx.x;
    const int w    = tid >> 5;
    const int lane = tid & 31;         // = batch b
    const int g    = w >> 2;           // column group
    const int r    = w & 3;            // k quarter
    const int k0   = r * 256;

    // reduction scratch inside hbuf, avoiding this CTA's own 8 rows
    float* red = hbuf + ((cta < 8) ? (64 * 32) : 0);

    // ---- preload this CTA's 24 weight rows into SMEM (once per layer) ----
    for (int rr = w; rr < 24; rr += 8) {
        int gj = (rr < 8)  ? (cta * 8 + rr)
               : (rr < 16) ? (H_ + cta * 8 + (rr - 8))
                           : (2 * H_ + cta * 8 + (rr - 16));
        const float* src = Wh + (size_t)gj * H_;
        if (rr < 16) {
            for (int k = lane; k < H_; k += 32) w_sA[k * 16 + rr] = src[k];
        } else {
            for (int k = lane; k < H_; k += 32) w_g[k * 8 + (rr - 16)] = src[k];
        }
    }

    // ---- init hidden state: g_hT[j][b] <- h0[b][layer][j] ----
    {
        int i = cta * 256 + tid;       // B*H = 32768 = grid*block
        int j = i >> 5, b = i & 31;
        g_hT[i] = h0[(b * L_ + layer) * H_ + j];
    }
    grid_barrier();

    const int j0A = cta * 8;           // base column of this CTA
    float4* dst4 = (float4*)hbuf;

    for (int s = 0; s < S_; s++) {
        // ---- prefetch xp for epilogues (warps 0 and 4 only) ----
        float4 xa0, xa1, xg;
        const size_t xpb = (size_t)(s * B_ + lane) * G3H + j0A;
        if (w == 0) {
            xa0 = *(const float4*)(xp + xpb);                 // z cols 0..3
            xa1 = *(const float4*)(xp + xpb + 4);             // z cols 4..7
            xg  = *(const float4*)(xp + xpb + 2 * H_);        // g cols 0..3
        } else if (w == 4) {
            xa0 = *(const float4*)(xp + xpb + H_);            // r cols 0..3
            xa1 = *(const float4*)(xp + xpb + H_ + 4);        // r cols 4..7
            xg  = *(const float4*)(xp + xpb + 2 * H_ + 4);    // g cols 4..7
        }

        // ---- stage h: g_hT -> hbuf (straight copy, both [j][b]) ----
        {
            const float4* src4 = (const float4*)g_hT;
            for (int i = tid; i < 8192; i += 256) dst4[i] = __ldcg(src4 + i);
        }
        __syncthreads();

        // ---- phase A accumulate: 8 cols (z or r), k in [k0, k0+256) ----
        ull a0 = 0, a1 = 0, a2 = 0, a3 = 0;
        {
            const float* hp = hbuf + lane;
            const float* wp = w_sA + g * 8;
#pragma unroll 4
            for (int k = k0; k < k0 + 256; k++) {
                float hv = hp[k * 32];
                ull hh = pk2(hv, hv);
                const ulonglong2* wv = (const ulonglong2*)(wp + k * 16);
                ulonglong2 u0 = wv[0];
                ulonglong2 u1 = wv[1];
                a0 = ffma2(hh, u0.x, a0);
                a1 = ffma2(hh, u0.y, a1);
                a2 = ffma2(hh, u1.x, a2);
                a3 = ffma2(hh, u1.y, a3);
            }
        }
        __syncthreads();
        if (r != 0) {
            ull* rp = (ull*)(red + (((g * 3) + (r - 1)) * 32 + lane) * 8);
            rp[0] = a0; rp[1] = a1; rp[2] = a2; rp[3] = a3;
        }
        __syncthreads();
        if (r == 0) {
#pragma unroll
            for (int t = 0; t < 3; t++) {
                const ull* rp = (const ull*)(red + (((g * 3) + t) * 32 + lane) * 8);
                a0 = fadd2(a0, rp[0]); a1 = fadd2(a1, rp[1]);
                a2 = fadd2(a2, rp[2]); a3 = fadd2(a3, rp[3]);
            }
            float out[8];
            upk2(a0, out[0], out[1]); upk2(a1, out[2], out[3]);
            upk2(a2, out[4], out[5]); upk2(a3, out[6], out[7]);
            float xv[8] = {xa0.x, xa0.y, xa0.z, xa0.w, xa1.x, xa1.y, xa1.z, xa1.w};
            if (w == 0) {            // z gate: keep CTA-local
#pragma unroll
                for (int c = 0; c < 8; c++) {
                    float zz = 1.f / (1.f + expf(-(out[c] + xv[c])));
                    s_z[lane * 8 + c] = zz;
                }
            } else {                 // r gate -> rh, write global [j][b]
#pragma unroll
                for (int c = 0; c < 8; c++) {
                    float rv = 1.f / (1.f + expf(-(out[c] + xv[c])));
                    float hov = hbuf[(j0A + c) * 32 + lane];
                    g_rhT[(j0A + c) * 32 + lane] = rv * hov;
                }
            }
        }
        grid_barrier();

        // ---- stage rh: g_rhT -> hbuf ----
        {
            const float4* src4 = (const float4*)g_rhT;
            for (int i = tid; i < 8192; i += 256) dst4[i] = __ldcg(src4 + i);
        }
        __syncthreads();

        // ---- phase B accumulate: 4 g-cols, same k quarter ----
        ull b0 = 0, b1 = 0;
        {
            const float* hp = hbuf + lane;
            const float* wp = w_g + g * 4;
#pragma unroll 4
            for (int k = k0; k < k0 + 256; k++) {
                float hv = hp[k * 32];
                ull hh = pk2(hv, hv);
                ulonglong2 u = *(const ulonglong2*)(wp + k * 8);
                b0 = ffma2(hh, u.x, b0);
                b1 = ffma2(hh, u.y, b1);
            }
        }
        __syncthreads();
        if (r != 0) {
            ull* rp = (ull*)(red + (((g * 3) + (r - 1)) * 32 + lane) * 4);
            rp[0] = b0; rp[1] = b1;
        }
        __syncthreads();
        if (r == 0) {
#pragma unroll
            for (int t = 0; t < 3; t++) {
                const ull* rp = (const ull*)(red + (((g * 3) + t) * 32 + lane) * 4);
                b0 = fadd2(b0, rp[0]); b1 = fadd2(b1, rp[1]);
            }
            float gout[4];
            upk2(b0, gout[0], gout[1]); upk2(b1, gout[2], gout[3]);
            float xgv[4] = {xg.x, xg.y, xg.z, xg.w};
            const int jb = j0A + g * 4;
            float hn[4];
#pragma unroll
            for (int c = 0; c < 4; c++) {
                float gg = tanhf(gout[c] + xgv[c]);
                float zz = s_z[lane * 8 + g * 4 + c];
                float ho = __ldcg(&g_hT[(jb + c) * 32 + lane]);
                hn[c] = zz * ho + (1.f - zz) * gg;
                g_hT[(jb + c) * 32 + lane] = hn[c];
            }
            float4 hv4 = make_float4(hn[0], hn[1], hn[2], hn[3]);
            *(float4*)(hs + (size_t)(s * B_ + lane) * H_ + jb) = hv4;
            if (s == S_ - 1)
                *(float4*)(hlast + (size_t)(lane * L_ + layer) * H_ + jb) = hv4;
        }
        grid_barrier();
    }
}

// ---------------- host launch ----------------
extern "C" void kernel_launch(void* const* d_in, const int* in_sizes, int n_in,
                              void* d_out, int out_size)
{
    const float* x    = (const float*)d_in[0];
    const float* h0   = (const float*)d_in[1];
    const float* Wx0  = (const float*)d_in[2];
    const float* Wh0  = (const float*)d_in[3];
    const float* bh0  = (const float*)d_in[4];
    const float* Wx   = (const float*)d_in[5];
    const float* Wh   = (const float*)d_in[6];
    const float* bh   = (const float*)d_in[7];
    const float* Wout = (const float*)d_in[8];
    const float* bout = (const float*)d_in[9];

    float* out = (float*)d_out;
    float* hid = out + (size_t)B_ * S_ * O_;

    float *p_xT, *p_xp, *p_hs;
    cudaGetSymbolAddress((void**)&p_xT, g_xT);
    cudaGetSymbolAddress((void**)&p_xp, g_xp);
    cudaGetSymbolAddress((void**)&p_hs, g_hs);

    cudaFuncSetAttribute(gru_rec_kernel,
                         cudaFuncAttributeMaxDynamicSharedMemorySize, 229376);

    // 1) transpose x -> [s*B+b][i]
    transpose_kernel<<<4096, 256>>>((const float4*)x, (float4*)p_xT);

    // 2) layer 0
    gemm_kernel<<<dim3(G3H / 128, (S_ * B_) / 128), 256>>>(p_xT, Wx0, bh0, p_xp, I_, G3H, 0);
    gru_rec_kernel<<<NCTA_REC, 256, 229376>>>(Wh0, p_xp, p_hs, h0, 0, hid);

    // 3) layer 1
    gemm_kernel<<<dim3(G3H / 128, (S_ * B_) / 128), 256>>>(p_hs, Wx, bh, p_xp, H_, G3H, 0);
    gru_rec_kernel<<<NCTA_REC, 256, 229376>>>(Wh, p_xp, p_hs, h0, 1, hid);

    // 4) layer 2
    gemm_kernel<<<dim3(G3H / 128, (S_ * B_) / 128), 256>>>(
        p_hs, Wx + (size_t)3 * H_ * H_, bh + 3 * H_, p_xp, H_, G3H, 0);
    gru_rec_kernel<<<NCTA_REC, 256, 229376>>>(
        Wh + (size_t)3 * H_ * H_, p_xp, p_hs, h0, 2, hid);

    // 5) output head -> d_out [B,S,O]
    gemm_kernel<<<dim3(O_ / 128, (S_ * B_) / 128), 256>>>(p_hs, Wout, bout, out, H_, O_, 1);
}